// round 2
// baseline (speedup 1.0000x reference)
#include <cuda_runtime.h>

#define BB 256
#define SS 4096
#define HH 64

// Layer ping-pong scratch (allocation-free: static device globals)
__device__ float g_buf0[(size_t)BB * SS * HH];
__device__ float g_buf1[(size_t)BB * SS * HH];

typedef unsigned long long ull;

// ---- packed f32x2 helpers (FFMA2 path, sm_103a) ----
__device__ __forceinline__ ull pk2(float lo, float hi) {
    ull r; asm("mov.b64 %0,{%1,%2};" : "=l"(r) : "f"(lo), "f"(hi)); return r;
}
__device__ __forceinline__ void upk2(ull v, float& lo, float& hi) {
    asm("mov.b64 {%0,%1},%2;" : "=f"(lo), "=f"(hi) : "l"(v));
}
__device__ __forceinline__ ull ffma2(ull a, ull b, ull c) {
    ull d; asm("fma.rn.f32x2 %0,%1,%2,%3;" : "=l"(d) : "l"(a), "l"(b), "l"(c)); return d;
}

// Activations via MUFU (err ~1e-6, far under 1e-3 budget)
__device__ __forceinline__ float sig_(float x) {
    float e = __expf(-x);
    return __fdividef(1.f, 1.f + e);
}
__device__ __forceinline__ float tanh_(float x) {
    float e = __expf(-2.f * x);
    return __fdividef(2.f, 1.f + e) - 1.f;
}

// LSTM layer scan. 128 CTAs x 256 threads; CTA owns 2 batch rows for all 4096
// steps. Thread j -> gate type q=j&3 (i,f,g,o), hidden hh=j>>2 (weight row
// q*64+hh in registers as packed f32x2). Gate values for one hidden unit live
// in one lane-quad -> gathered by SHFL, no SMEM round trip. ONE barrier/step:
// sh_h is parity double-buffered. The x-part FMAs for step t+1 (independent
// of h_t) overlap the c/h update chain.
template <bool L0>
__global__ __launch_bounds__(256, 1)
void lstm_scan(const float* __restrict__ xin,
               const float* __restrict__ Wih, const float* __restrict__ Whh,
               const float* __restrict__ bih, const float* __restrict__ bhh,
               float* __restrict__ hsout,
               float* __restrict__ hn, float* __restrict__ cn) {
    const int j = threadIdx.x;
    const int lane = j & 31;
    const int q = j & 3;            // gate type: 0=i,1=f,2=g,3=o
    const int hh = j >> 2;          // hidden index 0..63
    const int row = q * HH + hh;    // PyTorch weight row
    const int b0 = blockIdx.x * 2;

    __shared__ float4 sh_x[2][2][16];   // [slot][batch][64 floats] staged x (L1,L2)
    __shared__ float  sh_xs[2][2];      // [slot][batch] scalar x (L0)
    __shared__ float4 sh_h[2][2][16];   // [parity][batch][64 floats] h state

    // ---- weights into registers (packed f32x2) ----
    ull whr[32];   // Whh row
    ull wxr[32];   // Wih row (L1,L2)
    float w0 = 0.f;
    {
        const float4* Wr = reinterpret_cast<const float4*>(Whh + row * HH);
#pragma unroll
        for (int k = 0; k < 16; k++) {
            float4 v = Wr[k];
            whr[2 * k] = pk2(v.x, v.y);
            whr[2 * k + 1] = pk2(v.z, v.w);
        }
    }
    if (!L0) {
        const float4* Wr = reinterpret_cast<const float4*>(Wih + row * HH);
#pragma unroll
        for (int k = 0; k < 16; k++) {
            float4 v = Wr[k];
            wxr[2 * k] = pk2(v.x, v.y);
            wxr[2 * k + 1] = pk2(v.z, v.w);
        }
    } else {
        w0 = Wih[row];  // Wih0 is [256,1]
    }
    const float bias = bih[row] + bhh[row];

    // ---- init: zero h parity slot 0; prime x staging (x0->slot0, x1->slot1) ----
    if (j < 32) reinterpret_cast<float4*>(sh_h)[j] = make_float4(0.f, 0.f, 0.f, 0.f);

    float4 xpre = make_float4(0.f, 0.f, 0.f, 0.f);
    float xpres = 0.f;
    int lb = 0, li = 0;
    size_t xb4 = 0, xb1 = 0;
    if (!L0) {
        if (j < 32) {
            lb = j >> 4; li = j & 15;
            xb4 = (size_t)(b0 + lb) * SS * 16;
            const float4* xg = reinterpret_cast<const float4*>(xin);
            sh_x[0][lb][li] = xg[xb4 + li];        // x_0
            sh_x[1][lb][li] = xg[xb4 + 16 + li];   // x_1
            xpre = xg[xb4 + 32 + li];              // x_2
        }
    } else {
        if (j < 2) {
            xb1 = (size_t)(b0 + j) * SS;
            sh_xs[0][j] = xin[xb1];
            sh_xs[1][j] = xin[xb1 + 1];
            xpres = xin[xb1 + 2];
        }
    }
    __syncthreads();

    // ax = bias + Wih . x_t, computed one step ahead from staged SMEM slot.
    auto comp_ax = [&](int slot, float& A0o, float& A1o) {
        if (L0) {
            A0o = fmaf(w0, sh_xs[slot][0], bias);
            A1o = fmaf(w0, sh_xs[slot][1], bias);
        } else {
            ull a0a = pk2(bias, 0.f), a0b = pk2(0.f, 0.f);
            ull a1a = pk2(bias, 0.f), a1b = pk2(0.f, 0.f);
            const ulonglong2* vx = reinterpret_cast<const ulonglong2*>(sh_x[slot]);
#pragma unroll
            for (int k = 0; k < 8; k++) {
                ulonglong2 p0 = vx[k];
                ulonglong2 p1 = vx[8 + k];
                ulonglong2 p2 = vx[16 + k];
                ulonglong2 p3 = vx[24 + k];
                a0a = ffma2(wxr[2 * k],      p0.x, a0a);
                a0a = ffma2(wxr[2 * k + 1],  p0.y, a0a);
                a0b = ffma2(wxr[16 + 2 * k], p1.x, a0b);
                a0b = ffma2(wxr[17 + 2 * k], p1.y, a0b);
                a1a = ffma2(wxr[2 * k],      p2.x, a1a);
                a1a = ffma2(wxr[2 * k + 1],  p2.y, a1a);
                a1b = ffma2(wxr[16 + 2 * k], p3.x, a1b);
                a1b = ffma2(wxr[17 + 2 * k], p3.y, a1b);
            }
            float l, h;
            upk2(a0a, l, h); float s0 = l + h;
            upk2(a0b, l, h); s0 += l + h;
            upk2(a1a, l, h); float s1 = l + h;
            upk2(a1b, l, h); s1 += l + h;
            A0o = s0; A1o = s1;
        }
    };

    float ax0, ax1;
    comp_ax(0, ax0, ax1);   // ax for t=0
    __syncthreads();        // protect slot0 before its reuse at t=0

    float c = 0.f;          // lane q==0 carries batch b0, q==1 carries b0+1
    const int base = lane & ~3;

    for (int t = 0; t < SS; ++t) {
        const int pr = t & 1;

        // ---- h-part: g = ax + Whh . h_{t-1} (both batches) ----
        ull h0a = pk2(ax0, 0.f), h0b = pk2(0.f, 0.f);
        ull h1a = pk2(ax1, 0.f), h1b = pk2(0.f, 0.f);
        {
            const ulonglong2* vh = reinterpret_cast<const ulonglong2*>(sh_h[pr]);
#pragma unroll
            for (int k = 0; k < 8; k++) {
                ulonglong2 p0 = vh[k];
                ulonglong2 p1 = vh[8 + k];
                ulonglong2 p2 = vh[16 + k];
                ulonglong2 p3 = vh[24 + k];
                h0a = ffma2(whr[2 * k],      p0.x, h0a);
                h0a = ffma2(whr[2 * k + 1],  p0.y, h0a);
                h0b = ffma2(whr[16 + 2 * k], p1.x, h0b);
                h0b = ffma2(whr[17 + 2 * k], p1.y, h0b);
                h1a = ffma2(whr[2 * k],      p2.x, h1a);
                h1a = ffma2(whr[2 * k + 1],  p2.y, h1a);
                h1b = ffma2(whr[16 + 2 * k], p3.x, h1b);
                h1b = ffma2(whr[17 + 2 * k], p3.y, h1b);
            }
        }
        float l, h;
        upk2(h0a, l, h); float g0 = l + h;
        upk2(h0b, l, h); g0 += l + h;
        upk2(h1a, l, h); float g1 = l + h;
        upk2(h1b, l, h); g1 += l + h;

        // ---- activation (own gate, both batches) ----
        float A0, A1;
        if (q == 2) { A0 = tanh_(g0); A1 = tanh_(g1); }
        else        { A0 = sig_(g0);  A1 = sig_(g1); }

        // ---- quad gather via SHFL (all lanes converged) ----
        float i0 = __shfl_sync(0xffffffffu, A0, base + 0);
        float f0 = __shfl_sync(0xffffffffu, A0, base + 1);
        float gg0 = __shfl_sync(0xffffffffu, A0, base + 2);
        float o0 = __shfl_sync(0xffffffffu, A0, base + 3);
        float i1 = __shfl_sync(0xffffffffu, A1, base + 0);
        float f1 = __shfl_sync(0xffffffffu, A1, base + 1);
        float gg1 = __shfl_sync(0xffffffffu, A1, base + 2);
        float o1 = __shfl_sync(0xffffffffu, A1, base + 3);

        // ---- stage x_{t+2} into slot pr, prefetch x_{t+3} ----
        if (!L0) {
            if (j < 32) {
                sh_x[pr][lb][li] = xpre;
                int tt = t + 3;
                if (tt < SS) {
                    const float4* xg = reinterpret_cast<const float4*>(xin);
                    xpre = xg[xb4 + (size_t)tt * 16 + li];
                }
            }
        } else {
            if (j < 2) {
                sh_xs[pr][j] = xpres;
                int tt = t + 3;
                if (tt < SS) xpres = xin[xb1 + tt];
            }
        }

        // ---- ax for t+1 (independent of h_t: hides the update chain) ----
        comp_ax(pr ^ 1, ax0, ax1);

        // ---- c/h update: lane q==0 -> batch b0, q==1 -> batch b0+1 ----
        if (q < 2) {
            float iv, fv, gv, ov;
            if (q == 0) { iv = i0; fv = f0; gv = gg0; ov = o0; }
            else        { iv = i1; fv = f1; gv = gg1; ov = o1; }
            c = fv * c + iv * gv;
            float hv = ov * tanh_(c);
            reinterpret_cast<float*>(sh_h[pr ^ 1])[q * HH + hh] = hv;
            hsout[((size_t)(b0 + q) * SS + t) * HH + hh] = hv;
            if (t == SS - 1) {
                hn[(b0 + q) * HH + hh] = hv;
                cn[(b0 + q) * HH + hh] = c;
            }
        }
        __syncthreads();   // h_t + staged x visible for step t+1
    }
}

// Final projection: thread-per-output, 16 consecutive LDG.128 per thread (MLP 16).
__global__ __launch_bounds__(256)
void proj_kernel(const float* __restrict__ hs, const float* __restrict__ Wlin,
                 const float* __restrict__ blin, float* __restrict__ y) {
    __shared__ float4 w[16];
    __shared__ float bsh;
    if (threadIdx.x < 16) w[threadIdx.x] = reinterpret_cast<const float4*>(Wlin)[threadIdx.x];
    if (threadIdx.x == 16) bsh = blin[0];
    __syncthreads();
    size_t o = (size_t)blockIdx.x * 256 + threadIdx.x;
    const float4* v = reinterpret_cast<const float4*>(hs + o * HH);
    float acc = 0.f;
#pragma unroll
    for (int k = 0; k < 16; k++) {
        float4 a = v[k];
        float4 b = w[k];
        acc += a.x * b.x + a.y * b.y + a.z * b.z + a.w * b.w;
    }
    y[o] = acc + bsh;
}

extern "C" void kernel_launch(void* const* d_in, const int* in_sizes, int n_in,
                              void* d_out, int out_size) {
    const float* x    = (const float*)d_in[0];
    const float* Wih0 = (const float*)d_in[1];
    const float* Whh0 = (const float*)d_in[2];
    const float* bih0 = (const float*)d_in[3];
    const float* bhh0 = (const float*)d_in[4];
    const float* Wih1 = (const float*)d_in[5];
    const float* Whh1 = (const float*)d_in[6];
    const float* bih1 = (const float*)d_in[7];
    const float* bhh1 = (const float*)d_in[8];
    const float* Wih2 = (const float*)d_in[9];
    const float* Whh2 = (const float*)d_in[10];
    const float* bih2 = (const float*)d_in[11];
    const float* bhh2 = (const float*)d_in[12];
    const float* Wlin = (const float*)d_in[13];
    const float* blin = (const float*)d_in[14];

    float* y  = (float*)d_out;                 // [B,S,1]
    float* hn = y + (size_t)BB * SS;           // [3,B,H]
    float* cn = hn + (size_t)3 * BB * HH;      // [3,B,H]

    float *buf0, *buf1;
    cudaGetSymbolAddress((void**)&buf0, g_buf0);
    cudaGetSymbolAddress((void**)&buf1, g_buf1);

    lstm_scan<true ><<<BB / 2, 256>>>(x,    Wih0, Whh0, bih0, bhh0, buf0,
                                      hn,               cn);
    lstm_scan<false><<<BB / 2, 256>>>(buf0, Wih1, Whh1, bih1, bhh1, buf1,
                                      hn + BB * HH,     cn + BB * HH);
    lstm_scan<false><<<BB / 2, 256>>>(buf1, Wih2, Whh2, bih2, bhh2, buf0,
                                      hn + 2 * BB * HH, cn + 2 * BB * HH);

    proj_kernel<<<(BB * SS) / 256, 256>>>(buf0, Wlin, blin, y);
}

// round 3
// speedup vs baseline: 1.2088x; 1.2088x over previous
#include <cuda_runtime.h>

#define BB 256
#define SS 4096
#define HH 64
#define NG 256   // 4*H gates

// Layer ping-pong scratch (allocation-free: static device globals)
__device__ float g_buf0[(size_t)BB * SS * HH];
__device__ float g_buf1[(size_t)BB * SS * HH];

typedef unsigned long long ull;

// ---- packed f32x2 helpers (FFMA2 path, sm_103a) ----
__device__ __forceinline__ ull pk2(float lo, float hi) {
    ull r; asm("mov.b64 %0,{%1,%2};" : "=l"(r) : "f"(lo), "f"(hi)); return r;
}
__device__ __forceinline__ void upk2(ull v, float& lo, float& hi) {
    asm("mov.b64 {%0,%1},%2;" : "=f"(lo), "=f"(hi) : "l"(v));
}
__device__ __forceinline__ ull ffma2(ull a, ull b, ull c) {
    ull d; asm("fma.rn.f32x2 %0,%1,%2,%3;" : "=l"(d) : "l"(a), "l"(b), "l"(c)); return d;
}

// Activations via MUFU (err ~1e-6, far under 1e-3 budget)
__device__ __forceinline__ float sig_(float x) {
    float e = __expf(-x);
    return __fdividef(1.f, 1.f + e);
}
__device__ __forceinline__ float tanh_(float x) {
    float e = __expf(-2.f * x);
    return __fdividef(2.f, 1.f + e) - 1.f;
}

// LSTM layer scan, R1 structure with software-pipelined step:
//   pre-[C]:  g = ax_t + Whh.h_{t-1}  (64 ffma2) ; activation ; sh_act
//   post-[C]: ax_{t+1} = bias + Wih.x_{t+1} (64 ffma2, ALL threads)
//             overlapped with the c/h update on threads <128 and x staging.
// Thread j owns gate row j (PyTorch order), weight rows in registers.
template <bool L0>
__global__ __launch_bounds__(256, 1)
void lstm_scan(const float* __restrict__ xin,
               const float* __restrict__ Wih, const float* __restrict__ Whh,
               const float* __restrict__ bih, const float* __restrict__ bhh,
               float* __restrict__ hsout,
               float* __restrict__ hn, float* __restrict__ cn) {
    const int j = threadIdx.x;       // gate row 0..255
    const int b0 = blockIdx.x * 2;   // global batch base

    __shared__ float4 sh_x[2][2][16];  // [slot][batch][64 floats] (L1,L2)
    __shared__ float  sh_xs[2][2];     // [slot][batch] scalar x (L0)
    __shared__ float4 sh_h[2][16];     // [batch][64 floats] h_{t-1} (single buffer)
    __shared__ float  sh_act[2][NG];   // activated gates per batch

    // ---- weights into registers (packed f32x2) ----
    ull whr[32];
    ull wxr[32];
    float w0 = 0.f;
    {
        const float4* Wr = reinterpret_cast<const float4*>(Whh + j * HH);
#pragma unroll
        for (int k = 0; k < 16; k++) {
            float4 v = Wr[k];
            whr[2 * k] = pk2(v.x, v.y);
            whr[2 * k + 1] = pk2(v.z, v.w);
        }
    }
    if (!L0) {
        const float4* Wr = reinterpret_cast<const float4*>(Wih + j * HH);
#pragma unroll
        for (int k = 0; k < 16; k++) {
            float4 v = Wr[k];
            wxr[2 * k] = pk2(v.x, v.y);
            wxr[2 * k + 1] = pk2(v.z, v.w);
        }
    } else {
        w0 = Wih[j];  // Wih0 is [256,1]
    }
    const float bias = bih[j] + bhh[j];

    // ---- init: zero h; stage x_0 -> slot0, x_1 -> slot1; prefetch x_2 ----
    if (j < 32) reinterpret_cast<float4*>(sh_h)[j] = make_float4(0.f, 0.f, 0.f, 0.f);

    float4 xpre = make_float4(0.f, 0.f, 0.f, 0.f);
    float xpres = 0.f;
    int lb = 0, li = 0;
    size_t xb4 = 0, xb1 = 0;
    if (!L0) {
        if (j < 32) {
            lb = j >> 4; li = j & 15;
            xb4 = (size_t)(b0 + lb) * SS * 16;
            const float4* xg = reinterpret_cast<const float4*>(xin);
            sh_x[0][lb][li] = xg[xb4 + li];        // x_0
            sh_x[1][lb][li] = xg[xb4 + 16 + li];   // x_1
            xpre = xg[xb4 + 32 + li];              // x_2
        }
    } else {
        if (j < 2) {
            xb1 = (size_t)(b0 + j) * SS;
            sh_xs[0][j] = xin[xb1];
            sh_xs[1][j] = xin[xb1 + 1];
            xpres = xin[xb1 + 2];
        }
    }
    __syncthreads();

    // ax = bias + Wih.x  from staged slot (R1-style 2-accumulator loop)
    auto comp_ax = [&](int slot, float& A0o, float& A1o) {
        if (L0) {
            A0o = fmaf(w0, sh_xs[slot][0], bias);
            A1o = fmaf(w0, sh_xs[slot][1], bias);
        } else {
            ull a0 = pk2(bias, 0.f);
            ull a1 = pk2(bias, 0.f);
            const ulonglong2* vx = reinterpret_cast<const ulonglong2*>(sh_x[slot]);
#pragma unroll
            for (int k = 0; k < 16; k++) {
                ulonglong2 x0 = vx[k];
                ulonglong2 x1 = vx[16 + k];
                a0 = ffma2(wxr[2 * k], x0.x, a0);
                a0 = ffma2(wxr[2 * k + 1], x0.y, a0);
                a1 = ffma2(wxr[2 * k], x1.x, a1);
                a1 = ffma2(wxr[2 * k + 1], x1.y, a1);
            }
            float l, h;
            upk2(a0, l, h); A0o = l + h;
            upk2(a1, l, h); A1o = l + h;
        }
    };

    float ax0, ax1;
    comp_ax(0, ax0, ax1);   // ax for t=0 (reads slot0; first write to slot0 is post-[C] of t=0)

    float c = 0.f;

    for (int t = 0; t < SS; ++t) {
        // ---- [B] h-part: g = ax_t + Whh . h_{t-1} ----
        ull a0 = pk2(ax0, 0.f);
        ull a1 = pk2(ax1, 0.f);
        {
            const ulonglong2* vh = reinterpret_cast<const ulonglong2*>(sh_h);
#pragma unroll
            for (int k = 0; k < 16; k++) {
                ulonglong2 h0 = vh[k];
                ulonglong2 h1 = vh[16 + k];
                a0 = ffma2(whr[2 * k], h0.x, a0);
                a0 = ffma2(whr[2 * k + 1], h0.y, a0);
                a1 = ffma2(whr[2 * k], h1.x, a1);
                a1 = ffma2(whr[2 * k + 1], h1.y, a1);
            }
        }
        float l, h;
        upk2(a0, l, h); float g0 = l + h;
        upk2(a1, l, h); float g1 = l + h;

        float A0, A1;
        if ((j >> 6) == 2) { A0 = tanh_(g0); A1 = tanh_(g1); }
        else               { A0 = sig_(g0);  A1 = sig_(g1); }
        sh_act[0][j] = A0;
        sh_act[1][j] = A1;

        __syncthreads();  // [C] gates ready; h_{t-1} fully consumed

        // ---- stage x_{t+2} into slot (t&1); prefetch x_{t+3} ----
        const int slot_w = t & 1;
        if (!L0) {
            if (j < 32) {
                sh_x[slot_w][lb][li] = xpre;
                int tt = t + 3;
                if (tt < SS) {
                    const float4* xg = reinterpret_cast<const float4*>(xin);
                    xpre = xg[xb4 + (size_t)tt * 16 + li];
                }
            }
        } else {
            if (j < 2) {
                sh_xs[slot_w][j] = xpres;
                int tt = t + 3;
                if (tt < SS) xpres = xin[xb1 + tt];
            }
        }

        // ---- [D] update on threads <128, overlapped with ax_{t+1} below ----
        if (j < 128) {
            const int b = j >> 6, hh = j & 63;
            const float* A = sh_act[b];
            float iv = A[hh];
            float fv = A[64 + hh];
            float gv = A[128 + hh];
            float ov = A[192 + hh];
            c = fv * c + iv * gv;
            float hv = ov * tanh_(c);
            reinterpret_cast<float*>(sh_h)[b * HH + hh] = hv;
            hsout[((size_t)(b0 + b) * SS + t) * HH + hh] = hv;
            if (t == SS - 1) {
                hn[(b0 + b) * HH + hh] = hv;
                cn[(b0 + b) * HH + hh] = c;
            }
        }

        // ---- ax for t+1 (reads slot (t+1)&1, independent of h_t) ----
        comp_ax((t + 1) & 1, ax0, ax1);

        __syncthreads();  // [E] h_t + staged x visible for step t+1
    }
}

// Final projection: thread-per-output, 16 consecutive LDG.128 per thread.
__global__ __launch_bounds__(256)
void proj_kernel(const float* __restrict__ hs, const float* __restrict__ Wlin,
                 const float* __restrict__ blin, float* __restrict__ y) {
    __shared__ float4 w[16];
    __shared__ float bsh;
    if (threadIdx.x < 16) w[threadIdx.x] = reinterpret_cast<const float4*>(Wlin)[threadIdx.x];
    if (threadIdx.x == 16) bsh = blin[0];
    __syncthreads();
    size_t o = (size_t)blockIdx.x * 256 + threadIdx.x;
    const float4* v = reinterpret_cast<const float4*>(hs + o * HH);
    float acc = 0.f;
#pragma unroll
    for (int k = 0; k < 16; k++) {
        float4 a = v[k];
        float4 b = w[k];
        acc += a.x * b.x + a.y * b.y + a.z * b.z + a.w * b.w;
    }
    y[o] = acc + bsh;
}

extern "C" void kernel_launch(void* const* d_in, const int* in_sizes, int n_in,
                              void* d_out, int out_size) {
    const float* x    = (const float*)d_in[0];
    const float* Wih0 = (const float*)d_in[1];
    const float* Whh0 = (const float*)d_in[2];
    const float* bih0 = (const float*)d_in[3];
    const float* bhh0 = (const float*)d_in[4];
    const float* Wih1 = (const float*)d_in[5];
    const float* Whh1 = (const float*)d_in[6];
    const float* bih1 = (const float*)d_in[7];
    const float* bhh1 = (const float*)d_in[8];
    const float* Wih2 = (const float*)d_in[9];
    const float* Whh2 = (const float*)d_in[10];
    const float* bih2 = (const float*)d_in[11];
    const float* bhh2 = (const float*)d_in[12];
    const float* Wlin = (const float*)d_in[13];
    const float* blin = (const float*)d_in[14];

    float* y  = (float*)d_out;                 // [B,S,1]
    float* hn = y + (size_t)BB * SS;           // [3,B,H]
    float* cn = hn + (size_t)3 * BB * HH;      // [3,B,H]

    float *buf0, *buf1;
    cudaGetSymbolAddress((void**)&buf0, g_buf0);
    cudaGetSymbolAddress((void**)&buf1, g_buf1);

    lstm_scan<true ><<<BB / 2, 256>>>(x,    Wih0, Whh0, bih0, bhh0, buf0,
                                      hn,               cn);
    lstm_scan<false><<<BB / 2, 256>>>(buf0, Wih1, Whh1, bih1, bhh1, buf1,
                                      hn + BB * HH,     cn + BB * HH);
    lstm_scan<false><<<BB / 2, 256>>>(buf1, Wih2, Whh2, bih2, bhh2, buf0,
                                      hn + 2 * BB * HH, cn + 2 * BB * HH);

    proj_kernel<<<(BB * SS) / 256, 256>>>(buf0, Wlin, blin, y);
}